// round 5
// baseline (speedup 1.0000x reference)
#include <cuda_runtime.h>
#include <math.h>

// ---------------- scratch (device globals; no allocation allowed) ----------
__device__ float g_scores[512];         // attn logits
__device__ float g_ctx_part[8 * 2048];  // split-K context partials
__device__ float g_ctx[2048];           // reduced context
__device__ float g_x[2048];             // relu(attn_combine)
__device__ float g_gates[12288];        // gi[0:6144), gh[6144:12288)
__device__ float g_hnew[2048];          // new hidden
__device__ float g_lse[1];              // logsumexp of raw logits
__device__ float g_lmax[6284];          // per-block logits max
__device__ float g_lsum[6284];          // per-block sumexp
__device__ int   g_cnt_ctx;             // arrival counters (self-resetting)
__device__ int   g_cnt_gates;
__device__ int   g_cnt_logits;

#define H 2048
#define V 50257
#define L 512
#define NB_LOGITS 6283

__device__ __forceinline__ float warpSum(float v) {
#pragma unroll
    for (int o = 16; o; o >>= 1) v += __shfl_down_sync(0xffffffffu, v, o);
    return v;
}

// Dot of one 512-float4 (2048 float) weight segment vs smem vector segment.
// Front-batches all 16 LDG.128 with streaming (evict-first) hint.
__device__ __forceinline__ float warpDot512(const float4* __restrict__ w4,
                                            const float4* __restrict__ sv,
                                            int lane) {
    float4 wr[16];
#pragma unroll
    for (int j = 0; j < 16; j++) wr[j] = __ldcs(&w4[lane + 32 * j]);
    float a0 = 0.f, a1 = 0.f, a2 = 0.f, a3 = 0.f;
#pragma unroll
    for (int j = 0; j < 16; j++) {
        float4 v = sv[lane + 32 * j];
        a0 += wr[j].x * v.x;
        a1 += wr[j].y * v.y;
        a2 += wr[j].z * v.z;
        a3 += wr[j].w * v.w;
    }
    return warpSum((a0 + a1) + (a2 + a3));
}

// ---------------------------------------------------------------------------
// K1: attn scores. 2 warps/row, 4 rows/block, 128 blocks.
__global__ void __launch_bounds__(256, 3)
k_attn_scores(const int* __restrict__ token, const float* __restrict__ hidden,
              const float* __restrict__ embedding,
              const float* __restrict__ attn_W, const float* __restrict__ attn_b) {
    __shared__ float4 sv[1024];
    __shared__ float sred[8];
    int tid = threadIdx.x, lane = tid & 31, warp = tid >> 5;
    const float4* emb4 = (const float4*)(embedding + (size_t)__ldg(token) * H);
    const float4* hid4 = (const float4*)hidden;
#pragma unroll
    for (int k = 0; k < 2; k++) {
        int i = tid + 256 * k;
        sv[i] = __ldg(&emb4[i]);
        sv[i + 512] = __ldg(&hid4[i]);
    }
    __syncthreads();
    int row = blockIdx.x * 4 + (warp >> 1);
    int half = warp & 1;
    const float4* w4 = (const float4*)(attn_W + (size_t)row * 2 * H) + half * 512;
    float p = warpDot512(w4, sv + half * 512, lane);
    if (lane == 0) sred[warp] = p;
    __syncthreads();
    if (tid < 4) {
        int r = blockIdx.x * 4 + tid;
        g_scores[r] = sred[2 * tid] + sred[2 * tid + 1] + __ldg(&attn_b[r]);
    }
}

// ---------------------------------------------------------------------------
// K2: fused softmax + split-K context + final reduce.
// grid (8 col-tiles, 8 row-tiles) = 64 blocks, 256 threads.
// Every block recomputes the 512-wide softmax locally (cheap, deterministic).
// Block (0,0) writes attn weights to output. Last-arriving block reduces the
// 8 partials into g_ctx (fixed order -> deterministic).
__global__ void k_context(const float* __restrict__ enc,
                          float* __restrict__ out_aw) {
    __shared__ float s_e[L];     // exp(score - m)
    __shared__ float sred[16];
    int tid = threadIdx.x, lane = tid & 31, warp = tid >> 5;
    // local softmax over g_scores[512] with 256 threads (2 elems each)
    float v0 = g_scores[tid], v1 = g_scores[tid + 256];
    float m = fmaxf(v0, v1);
#pragma unroll
    for (int o = 16; o; o >>= 1) m = fmaxf(m, __shfl_down_sync(0xffffffffu, m, o));
    if (lane == 0) sred[warp] = m;
    __syncthreads();
    if (warp == 0) {
        m = (lane < 8) ? sred[lane] : -1e30f;
#pragma unroll
        for (int o = 4; o; o >>= 1) m = fmaxf(m, __shfl_down_sync(0xffffffffu, m, o));
        if (lane == 0) sred[8] = m;
    }
    __syncthreads();
    m = sred[8];
    float e0 = expf(v0 - m), e1 = expf(v1 - m);
    s_e[tid] = e0;
    s_e[tid + 256] = e1;
    float sum = warpSum(e0 + e1);
    if (lane == 0) sred[warp] = sum;
    __syncthreads();
    if (warp == 0) {
        sum = (lane < 8) ? sred[lane] : 0.f;
        sum = warpSum(sum);
        if (lane == 0) sred[9] = sum;
    }
    __syncthreads();
    float inv = 1.f / sred[9];
    if (blockIdx.x == 0 && blockIdx.y == 0) {
        out_aw[tid] = s_e[tid] * inv;
        out_aw[tid + 256] = s_e[tid + 256] * inv;
    }
    // partial context: rows [64*by, 64*by+64), cols [256*bx, 256*bx+256)
    int r0 = blockIdx.y * 64;
    int col = blockIdx.x * 256 + tid;
    float a0 = 0.f, a1 = 0.f, a2 = 0.f, a3 = 0.f;
#pragma unroll 4
    for (int l = 0; l < 64; l += 4) {
        a0 += s_e[r0 + l + 0] * __ldcs(&enc[(size_t)(r0 + l + 0) * H + col]);
        a1 += s_e[r0 + l + 1] * __ldcs(&enc[(size_t)(r0 + l + 1) * H + col]);
        a2 += s_e[r0 + l + 2] * __ldcs(&enc[(size_t)(r0 + l + 2) * H + col]);
        a3 += s_e[r0 + l + 3] * __ldcs(&enc[(size_t)(r0 + l + 3) * H + col]);
    }
    g_ctx_part[blockIdx.y * H + col] = ((a0 + a1) + (a2 + a3)) * inv;

    // last block reduces partials -> g_ctx
    __threadfence();
    __shared__ bool isLast;
    if (tid == 0) isLast = (atomicAdd(&g_cnt_ctx, 1) == 63);
    __syncthreads();
    if (isLast) {
        const float4* p4 = (const float4*)g_ctx_part;
#pragma unroll
        for (int k = 0; k < 2; k++) {
            int i = tid + 256 * k;       // 0..511 float4 cols
            float4 c = p4[i];
#pragma unroll
            for (int p = 1; p < 8; p++) {
                float4 q = p4[p * (H / 4) + i];
                c.x += q.x; c.y += q.y; c.z += q.z; c.w += q.w;
            }
            ((float4*)g_ctx)[i] = c;
        }
        if (tid == 0) g_cnt_ctx = 0;
    }
}

// ---------------------------------------------------------------------------
// K3: combine. 2 warps/row, 4 rows/block, 512 blocks. Stages cat(emb, ctx).
__global__ void __launch_bounds__(256, 3)
k_combine(const int* __restrict__ token, const float* __restrict__ embedding,
          const float* __restrict__ comb_W, const float* __restrict__ comb_b) {
    __shared__ float4 sv[1024];
    __shared__ float sred[8];
    int tid = threadIdx.x, lane = tid & 31, warp = tid >> 5;
    const float4* emb4 = (const float4*)(embedding + (size_t)__ldg(token) * H);
    const float4* ctx4 = (const float4*)g_ctx;
#pragma unroll
    for (int k = 0; k < 2; k++) {
        int i = tid + 256 * k;
        sv[i] = __ldg(&emb4[i]);
        sv[i + 512] = __ldg(&ctx4[i]);
    }
    __syncthreads();
    int row = blockIdx.x * 4 + (warp >> 1);
    int half = warp & 1;
    const float4* w4 = (const float4*)(comb_W + (size_t)row * 2 * H) + half * 512;
    float p = warpDot512(w4, sv + half * 512, lane);
    if (lane == 0) sred[warp] = p;
    __syncthreads();
    if (tid < 4) {
        int r = blockIdx.x * 4 + tid;
        g_x[r] = fmaxf(sred[2 * tid] + sred[2 * tid + 1] + __ldg(&comb_b[r]), 0.f);
    }
}

// ---------------------------------------------------------------------------
// K4: GRU gates + fused h_new tail. 1 warp/row, 8 rows/block, 1536 blocks.
__global__ void __launch_bounds__(256, 3)
k_gates(const float* __restrict__ w_ih, const float* __restrict__ w_hh,
        const float* __restrict__ b_ih, const float* __restrict__ b_hh,
        const float* __restrict__ hidden, float* __restrict__ out_h) {
    __shared__ float4 sv[512];
    int tid = threadIdx.x, lane = tid & 31, warp = tid >> 5;
    bool ih = blockIdx.x < 768;
    const float4* v4 = ih ? (const float4*)g_x : (const float4*)hidden;
#pragma unroll
    for (int k = 0; k < 2; k++) sv[tid + 256 * k] = __ldg(&v4[tid + 256 * k]);
    __syncthreads();
    int row = blockIdx.x * 8 + warp;
    int lrow = ih ? row : row - 3 * H;
    const float* W = ih ? w_ih : w_hh;
    const float4* w4 = (const float4*)(W + (size_t)lrow * H);
    float a = warpDot512(w4, sv, lane);
    if (lane == 0)
        g_gates[row] = a + __ldg(ih ? &b_ih[lrow] : &b_hh[lrow]);

    // last block computes h_new
    __threadfence();
    __shared__ bool isLast;
    if (tid == 0) isLast = (atomicAdd(&g_cnt_gates, 1) == 1535);
    __syncthreads();
    if (isLast) {
        const float* gi = g_gates;
        const float* gh = g_gates + 3 * H;
#pragma unroll
        for (int k = 0; k < 8; k++) {
            int i = tid + 256 * k;       // 0..2047
            float r = 1.f / (1.f + expf(-(gi[i] + gh[i])));
            float z = 1.f / (1.f + expf(-(gi[H + i] + gh[H + i])));
            float n = tanhf(gi[2 * H + i] + r * gh[2 * H + i]);
            float hn = (1.f - z) * n + z * hidden[i];
            g_hnew[i] = hn;
            out_h[i] = hn;
        }
        if (tid == 0) g_cnt_gates = 0;
    }
}

// ---------------------------------------------------------------------------
// K5: logits GEMV (412 MB) + fused per-block (max, sumexp) partial + final
// logsumexp merge in the last-arriving block.
__global__ void __launch_bounds__(256, 3)
k_logits(const float* __restrict__ out_W, const float* __restrict__ out_b,
         float* __restrict__ out) {
    __shared__ float4 sv[512];
    __shared__ float srow[8];
    int tid = threadIdx.x, lane = tid & 31, warp = tid >> 5;
    const float4* v4 = (const float4*)g_hnew;
#pragma unroll
    for (int k = 0; k < 2; k++) sv[tid + 256 * k] = __ldg(&v4[tid + 256 * k]);
    __syncthreads();
    int row = blockIdx.x * 8 + warp;
    bool valid = (row < V);
    float val = -1e30f;
    if (valid) {
        const float4* w4 = (const float4*)(out_W + (size_t)row * H);
        float a = warpDot512(w4, sv, lane);
        val = a + __ldg(&out_b[row]);
        if (lane == 0) out[row] = val;
    }
    if (lane == 0) srow[warp] = valid ? val : -1e30f;
    __syncthreads();
    // per-block (m, s) partial over its <=8 rows
    if (tid == 0) {
        float m = srow[0];
#pragma unroll
        for (int k = 1; k < 8; k++) m = fmaxf(m, srow[k]);
        float s = 0.f;
#pragma unroll
        for (int k = 0; k < 8; k++) s += expf(srow[k] - m);
        g_lmax[blockIdx.x] = m;
        g_lsum[blockIdx.x] = s;
    }
    __threadfence();
    __shared__ bool isLast;
    if (tid == 0) isLast = (atomicAdd(&g_cnt_logits, 1) == NB_LOGITS - 1);
    __syncthreads();
    if (isLast) {
        __shared__ float smm[8], sss[8];
        // fixed-order online merge per thread, then tree merge
        float m = -1e30f, s = 0.f;
        for (int i = tid; i < NB_LOGITS; i += 256) {
            float m2 = g_lmax[i], s2 = g_lsum[i];
            float M = fmaxf(m, m2);
            s = s * expf(m - M) + s2 * expf(m2 - M);
            m = M;
        }
#pragma unroll
        for (int o = 16; o; o >>= 1) {
            float m2 = __shfl_down_sync(0xffffffffu, m, o);
            float s2 = __shfl_down_sync(0xffffffffu, s, o);
            float M = fmaxf(m, m2);
            s = s * expf(m - M) + s2 * expf(m2 - M);
            m = M;
        }
        if (lane == 0) { smm[warp] = m; sss[warp] = s; }
        __syncthreads();
        if (tid == 0) {
            m = smm[0]; s = sss[0];
#pragma unroll
            for (int k = 1; k < 8; k++) {
                float M = fmaxf(m, smm[k]);
                s = s * expf(m - M) + sss[k] * expf(smm[k] - M);
                m = M;
            }
            g_lse[0] = m + logf(s);
            g_cnt_logits = 0;
        }
    }
}

// K6: out[v] -= lse
__global__ void k_logsoftmax(float* __restrict__ out) {
    int i = blockIdx.x * blockDim.x + threadIdx.x;
    if (i < V) out[i] -= g_lse[0];
}

extern "C" void kernel_launch(void* const* d_in, const int* in_sizes, int n_in,
                              void* d_out, int out_size) {
    const int*   token     = (const int*)d_in[0];
    const float* hidden    = (const float*)d_in[1];
    const float* enc       = (const float*)d_in[2];
    const float* embedding = (const float*)d_in[3];
    const float* attn_W    = (const float*)d_in[4];
    const float* attn_b    = (const float*)d_in[5];
    const float* comb_W    = (const float*)d_in[6];
    const float* comb_b    = (const float*)d_in[7];
    const float* w_ih      = (const float*)d_in[8];
    const float* w_hh      = (const float*)d_in[9];
    const float* b_ih      = (const float*)d_in[10];
    const float* b_hh      = (const float*)d_in[11];
    const float* out_W     = (const float*)d_in[12];
    const float* out_b     = (const float*)d_in[13];

    float* out = (float*)d_out;
    float* out_logits = out;
    float* out_h      = out + V;
    float* out_aw     = out + V + H;

    k_attn_scores<<<L / 4, 256>>>(token, hidden, embedding, attn_W, attn_b);
    k_context<<<dim3(8, 8), 256>>>(enc, out_aw);
    k_combine<<<H / 4, 256>>>(token, embedding, comb_W, comb_b);
    k_gates<<<6 * H / 8, 256>>>(w_ih, w_hh, b_ih, b_hh, hidden, out_h);
    k_logits<<<NB_LOGITS, 256>>>(out_W, out_b, out_logits);
    k_logsoftmax<<<(V + 255) / 256, 256>>>(out_logits);
}

// round 6
// speedup vs baseline: 1.1437x; 1.1437x over previous
#include <cuda_runtime.h>
#include <math.h>

// ---------------- scratch (device globals; no allocation allowed) ----------
__device__ float g_scores[512];         // attn logits
__device__ float g_ctx_part[8 * 2048];  // split-K context partials
__device__ float g_ctx[2048];           // reduced context
__device__ float g_x[2048];             // relu(attn_combine)
__device__ float g_gates[12288];        // gi[0:6144), gh[6144:12288)
__device__ float g_hnew[2048];          // new hidden
__device__ float g_lse[1];              // logsumexp of raw logits
__device__ float g_lmax[512];           // per-block logits max partials
__device__ float g_lsum[512];           // per-block sumexp partials
__device__ int   g_cnt_ctx;             // ctx arrival counter (self-resetting)

#define H 2048
#define V 50257
#define L 512
#define NB_PERSIST 444                  // 148 SMs x occupancy 3

__device__ __forceinline__ float warpSum(float v) {
#pragma unroll
    for (int o = 16; o; o >>= 1) v += __shfl_down_sync(0xffffffffu, v, o);
    return v;
}

// Dot of one 512-float4 (2048 float) weight segment vs smem vector segment.
// Front-batches all 16 LDG.128 with streaming (evict-first) hint.
__device__ __forceinline__ float warpDot512(const float4* __restrict__ w4,
                                            const float4* __restrict__ sv,
                                            int lane) {
    float4 wr[16];
#pragma unroll
    for (int j = 0; j < 16; j++) wr[j] = __ldcs(&w4[lane + 32 * j]);
    float a0 = 0.f, a1 = 0.f, a2 = 0.f, a3 = 0.f;
#pragma unroll
    for (int j = 0; j < 16; j++) {
        float4 v = sv[lane + 32 * j];
        a0 += wr[j].x * v.x;
        a1 += wr[j].y * v.y;
        a2 += wr[j].z * v.z;
        a3 += wr[j].w * v.w;
    }
    return warpSum((a0 + a1) + (a2 + a3));
}

// ---------------------------------------------------------------------------
// K1: attn scores. 2 warps/row, 4 rows/block, 128 blocks.
__global__ void __launch_bounds__(256, 3)
k_attn_scores(const int* __restrict__ token, const float* __restrict__ hidden,
              const float* __restrict__ embedding,
              const float* __restrict__ attn_W, const float* __restrict__ attn_b) {
    __shared__ float4 sv[1024];
    __shared__ float sred[8];
    int tid = threadIdx.x, lane = tid & 31, warp = tid >> 5;
    const float4* emb4 = (const float4*)(embedding + (size_t)__ldg(token) * H);
    const float4* hid4 = (const float4*)hidden;
#pragma unroll
    for (int k = 0; k < 2; k++) {
        int i = tid + 256 * k;
        sv[i] = __ldg(&emb4[i]);
        sv[i + 512] = __ldg(&hid4[i]);
    }
    __syncthreads();
    int row = blockIdx.x * 4 + (warp >> 1);
    int half = warp & 1;
    const float4* w4 = (const float4*)(attn_W + (size_t)row * 2 * H) + half * 512;
    float p = warpDot512(w4, sv + half * 512, lane);
    if (lane == 0) sred[warp] = p;
    __syncthreads();
    if (tid < 4) {
        int r = blockIdx.x * 4 + tid;
        g_scores[r] = sred[2 * tid] + sred[2 * tid + 1] + __ldg(&attn_b[r]);
    }
}

// ---------------------------------------------------------------------------
// K2: fused softmax + split-K context + last-block reduce (64 blocks only,
// so the per-block fence cost is negligible here).
__global__ void k_context(const float* __restrict__ enc,
                          float* __restrict__ out_aw) {
    __shared__ float s_e[L];
    __shared__ float sred[16];
    int tid = threadIdx.x, lane = tid & 31, warp = tid >> 5;
    float v0 = g_scores[tid], v1 = g_scores[tid + 256];
    float m = fmaxf(v0, v1);
#pragma unroll
    for (int o = 16; o; o >>= 1) m = fmaxf(m, __shfl_down_sync(0xffffffffu, m, o));
    if (lane == 0) sred[warp] = m;
    __syncthreads();
    if (warp == 0) {
        m = (lane < 8) ? sred[lane] : -1e30f;
#pragma unroll
        for (int o = 4; o; o >>= 1) m = fmaxf(m, __shfl_down_sync(0xffffffffu, m, o));
        if (lane == 0) sred[8] = m;
    }
    __syncthreads();
    m = sred[8];
    float e0 = expf(v0 - m), e1 = expf(v1 - m);
    s_e[tid] = e0;
    s_e[tid + 256] = e1;
    float sum = warpSum(e0 + e1);
    if (lane == 0) sred[warp] = sum;
    __syncthreads();
    if (warp == 0) {
        sum = (lane < 8) ? sred[lane] : 0.f;
        sum = warpSum(sum);
        if (lane == 0) sred[9] = sum;
    }
    __syncthreads();
    float inv = 1.f / sred[9];
    if (blockIdx.x == 0 && blockIdx.y == 0) {
        out_aw[tid] = s_e[tid] * inv;
        out_aw[tid + 256] = s_e[tid + 256] * inv;
    }
    int r0 = blockIdx.y * 64;
    int col = blockIdx.x * 256 + tid;
    float a0 = 0.f, a1 = 0.f, a2 = 0.f, a3 = 0.f;
#pragma unroll 4
    for (int l = 0; l < 64; l += 4) {
        a0 += s_e[r0 + l + 0] * __ldcs(&enc[(size_t)(r0 + l + 0) * H + col]);
        a1 += s_e[r0 + l + 1] * __ldcs(&enc[(size_t)(r0 + l + 1) * H + col]);
        a2 += s_e[r0 + l + 2] * __ldcs(&enc[(size_t)(r0 + l + 2) * H + col]);
        a3 += s_e[r0 + l + 3] * __ldcs(&enc[(size_t)(r0 + l + 3) * H + col]);
    }
    g_ctx_part[blockIdx.y * H + col] = ((a0 + a1) + (a2 + a3)) * inv;

    __threadfence();
    __shared__ bool isLast;
    if (tid == 0) isLast = (atomicAdd(&g_cnt_ctx, 1) == 63);
    __syncthreads();
    if (isLast) {
        const float4* p4 = (const float4*)g_ctx_part;
#pragma unroll
        for (int k = 0; k < 2; k++) {
            int i = tid + 256 * k;
            float4 c = p4[i];
#pragma unroll
            for (int p = 1; p < 8; p++) {
                float4 q = p4[p * (H / 4) + i];
                c.x += q.x; c.y += q.y; c.z += q.z; c.w += q.w;
            }
            ((float4*)g_ctx)[i] = c;
        }
        if (tid == 0) g_cnt_ctx = 0;
    }
}

// ---------------------------------------------------------------------------
// K3: combine. 2 warps/row, 4 rows/block, 512 blocks.
__global__ void __launch_bounds__(256, 3)
k_combine(const int* __restrict__ token, const float* __restrict__ embedding,
          const float* __restrict__ comb_W, const float* __restrict__ comb_b) {
    __shared__ float4 sv[1024];
    __shared__ float sred[8];
    int tid = threadIdx.x, lane = tid & 31, warp = tid >> 5;
    const float4* emb4 = (const float4*)(embedding + (size_t)__ldg(token) * H);
    const float4* ctx4 = (const float4*)g_ctx;
#pragma unroll
    for (int k = 0; k < 2; k++) {
        int i = tid + 256 * k;
        sv[i] = __ldg(&emb4[i]);
        sv[i + 512] = __ldg(&ctx4[i]);
    }
    __syncthreads();
    int row = blockIdx.x * 4 + (warp >> 1);
    int half = warp & 1;
    const float4* w4 = (const float4*)(comb_W + (size_t)row * 2 * H) + half * 512;
    float p = warpDot512(w4, sv + half * 512, lane);
    if (lane == 0) sred[warp] = p;
    __syncthreads();
    if (tid < 4) {
        int r = blockIdx.x * 4 + tid;
        g_x[r] = fmaxf(sred[2 * tid] + sred[2 * tid + 1] + __ldg(&comb_b[r]), 0.f);
    }
}

// ---------------------------------------------------------------------------
// K4: GRU gates, PERSISTENT. 444 blocks; stage x and hidden once; each warp
// loops over rows 0..12287 with stride 3552. No fences.
__global__ void __launch_bounds__(256, 3)
k_gates(const float* __restrict__ w_ih, const float* __restrict__ w_hh,
        const float* __restrict__ b_ih, const float* __restrict__ b_hh,
        const float* __restrict__ hidden) {
    __shared__ float4 sv[1024];   // [0:512)=x, [512:1024)=hidden
    int tid = threadIdx.x, lane = tid & 31, warp = tid >> 5;
    const float4* x4 = (const float4*)g_x;
    const float4* h4 = (const float4*)hidden;
#pragma unroll
    for (int k = 0; k < 2; k++) {
        int i = tid + 256 * k;
        sv[i] = __ldg(&x4[i]);
        sv[i + 512] = __ldg(&h4[i]);
    }
    __syncthreads();
    for (int row = blockIdx.x * 8 + warp; row < 6 * H; row += NB_PERSIST * 8) {
        bool ih = row < 3 * H;
        int lrow = ih ? row : row - 3 * H;
        const float* W = ih ? w_ih : w_hh;
        const float4* w4 = (const float4*)(W + (size_t)lrow * H);
        float a = warpDot512(w4, ih ? sv : sv + 512, lane);
        if (lane == 0)
            g_gates[row] = a + __ldg(ih ? &b_ih[lrow] : &b_hh[lrow]);
    }
}

// ---------------------------------------------------------------------------
// K5: GRU gate combine -> h_new
__global__ void k_hnew(const float* __restrict__ hidden, float* __restrict__ out_h) {
    int i = blockIdx.x * blockDim.x + threadIdx.x;
    if (i >= H) return;
    const float* gi = g_gates;
    const float* gh = g_gates + 3 * H;
    float r = 1.f / (1.f + expf(-(gi[i] + gh[i])));
    float z = 1.f / (1.f + expf(-(gi[H + i] + gh[H + i])));
    float n = tanhf(gi[2 * H + i] + r * gh[2 * H + i]);
    float hn = (1.f - z) * n + z * hidden[i];
    g_hnew[i] = hn;
    out_h[i] = hn;
}

// ---------------------------------------------------------------------------
// K6: logits GEMV (412 MB), PERSISTENT, 444 blocks. Each warp loops over rows
// with stride 3552, keeping a running (max, sumexp) in lane 0. Block partial
// written with plain stores; launch boundary orders it (no fence, no atomic).
__global__ void __launch_bounds__(256, 3)
k_logits(const float* __restrict__ out_W, const float* __restrict__ out_b,
         float* __restrict__ out) {
    __shared__ float4 sv[512];
    __shared__ float smm[8], sss[8];
    int tid = threadIdx.x, lane = tid & 31, warp = tid >> 5;
    const float4* v4 = (const float4*)g_hnew;
#pragma unroll
    for (int k = 0; k < 2; k++) sv[tid + 256 * k] = __ldg(&v4[tid + 256 * k]);
    __syncthreads();
    float pm = -1e30f, ps = 0.f;   // lane-0 running (max, sumexp)
    for (int row = blockIdx.x * 8 + warp; row < V; row += NB_PERSIST * 8) {
        const float4* w4 = (const float4*)(out_W + (size_t)row * H);
        float a = warpDot512(w4, sv, lane);
        if (lane == 0) {
            float val = a + __ldg(&out_b[row]);
            out[row] = val;
            float M = fmaxf(pm, val);
            ps = ps * expf(pm - M) + expf(val - M);
            pm = M;
        }
    }
    if (lane == 0) { smm[warp] = pm; sss[warp] = ps; }
    __syncthreads();
    if (tid == 0) {
        float m = smm[0], s = sss[0];
#pragma unroll
        for (int k = 1; k < 8; k++) {
            float M = fmaxf(m, smm[k]);
            s = s * expf(m - M) + sss[k] * expf(smm[k] - M);
            m = M;
        }
        g_lmax[blockIdx.x] = m;
        g_lsum[blockIdx.x] = s;
    }
}

// ---------------------------------------------------------------------------
// K7: merge 444 block partials -> g_lse (1 block, 256 threads, ~3.5 KB read)
__global__ void k_lse_merge() {
    __shared__ float smm[8], sss[8];
    int tid = threadIdx.x, lane = tid & 31, warp = tid >> 5;
    float m = -1e30f, s = 0.f;
    for (int i = tid; i < NB_PERSIST; i += 256) {
        float m2 = g_lmax[i], s2 = g_lsum[i];
        float M = fmaxf(m, m2);
        s = s * expf(m - M) + s2 * expf(m2 - M);
        m = M;
    }
#pragma unroll
    for (int o = 16; o; o >>= 1) {
        float m2 = __shfl_down_sync(0xffffffffu, m, o);
        float s2 = __shfl_down_sync(0xffffffffu, s, o);
        float M = fmaxf(m, m2);
        s = s * expf(m - M) + s2 * expf(m2 - M);
        m = M;
    }
    if (lane == 0) { smm[warp] = m; sss[warp] = s; }
    __syncthreads();
    if (tid == 0) {
        m = smm[0]; s = sss[0];
#pragma unroll
        for (int k = 1; k < 8; k++) {
            float M = fmaxf(m, smm[k]);
            s = s * expf(m - M) + sss[k] * expf(smm[k] - M);
            m = M;
        }
        g_lse[0] = m + logf(s);
    }
}

// K8: out[v] -= lse
__global__ void k_logsoftmax(float* __restrict__ out) {
    int i = blockIdx.x * blockDim.x + threadIdx.x;
    if (i < V) out[i] -= g_lse[0];
}

extern "C" void kernel_launch(void* const* d_in, const int* in_sizes, int n_in,
                              void* d_out, int out_size) {
    const int*   token     = (const int*)d_in[0];
    const float* hidden    = (const float*)d_in[1];
    const float* enc       = (const float*)d_in[2];
    const float* embedding = (const float*)d_in[3];
    const float* attn_W    = (const float*)d_in[4];
    const float* attn_b    = (const float*)d_in[5];
    const float* comb_W    = (const float*)d_in[6];
    const float* comb_b    = (const float*)d_in[7];
    const float* w_ih      = (const float*)d_in[8];
    const float* w_hh      = (const float*)d_in[9];
    const float* b_ih      = (const float*)d_in[10];
    const float* b_hh      = (const float*)d_in[11];
    const float* out_W     = (const float*)d_in[12];
    const float* out_b     = (const float*)d_in[13];

    float* out = (float*)d_out;
    float* out_logits = out;
    float* out_h      = out + V;
    float* out_aw     = out + V + H;

    k_attn_scores<<<L / 4, 256>>>(token, hidden, embedding, attn_W, attn_b);
    k_context<<<dim3(8, 8), 256>>>(enc, out_aw);
    k_combine<<<H / 4, 256>>>(token, embedding, comb_W, comb_b);
    k_gates<<<NB_PERSIST, 256>>>(w_ih, w_hh, b_ih, b_hh, hidden);
    k_hnew<<<H / 256, 256>>>(hidden, out_h);
    k_logits<<<NB_PERSIST, 256>>>(out_W, out_b, out_logits);
    k_lse_merge<<<1, 256>>>();
    k_logsoftmax<<<(V + 255) / 256, 256>>>(out_logits);
}

// round 7
// speedup vs baseline: 1.1622x; 1.0162x over previous
#include <cuda_runtime.h>
#include <math.h>

// ---------------- scratch (device globals; no allocation allowed) ----------
__device__ float g_scores[512];         // attn logits
__device__ float g_ctx_part[8 * 2048];  // split-K context partials
__device__ float g_ctx[2048];           // reduced context
__device__ float g_x[2048];             // relu(attn_combine)
__device__ float g_gates[12288];        // gi[0:6144), gh[6144:12288)
__device__ float g_hnew[2048];          // new hidden
__device__ float g_lse[1];              // logsumexp of raw logits
__device__ float g_lmax[512];           // per-block logits max partials
__device__ float g_lsum[512];           // per-block sumexp partials
__device__ int   g_cnt_ctx;             // ctx arrival counter (self-resetting)

#define H 2048
#define V 50257
#define L 512
#define NB_LOGITS 444                   // persistent grid for logits
#define NB_GATES 384                    // 3072 warps x exactly 4 rows

__device__ __forceinline__ float warpSum(float v) {
#pragma unroll
    for (int o = 16; o; o >>= 1) v += __shfl_down_sync(0xffffffffu, v, o);
    return v;
}

// Load one chunk (8 float4 per lane = 256 float4) streaming.
__device__ __forceinline__ void loadChunk(float4* dst, const float4* __restrict__ w4,
                                          int lane) {
#pragma unroll
    for (int j = 0; j < 8; j++) dst[j] = __ldcs(&w4[lane + 32 * j]);
}
// FMA one chunk against an smem chunk; returns partial (no reduce).
__device__ __forceinline__ float dotChunk(const float4* wr, const float4* __restrict__ sv,
                                          int lane) {
    float a0 = 0.f, a1 = 0.f, a2 = 0.f, a3 = 0.f;
#pragma unroll
    for (int j = 0; j < 8; j++) {
        float4 v = sv[lane + 32 * j];
        a0 += wr[j].x * v.x;
        a1 += wr[j].y * v.y;
        a2 += wr[j].z * v.z;
        a3 += wr[j].w * v.w;
    }
    return (a0 + a1) + (a2 + a3);
}

// In-row pipelined dot over NC chunks (row = NC*256 float4).
template <int NC>
__device__ __forceinline__ float warpRowDot(const float4* __restrict__ w4,
                                            const float4* __restrict__ sv,
                                            int lane) {
    float4 A[8], B[8];
    loadChunk(A, w4, lane);
    float acc = 0.f;
#pragma unroll
    for (int c = 0; c < NC; c++) {
        float4* cur = (c & 1) ? B : A;
        float4* nxt = (c & 1) ? A : B;
        if (c + 1 < NC) loadChunk(nxt, w4 + (c + 1) * 256, lane);
        acc += dotChunk(cur, sv + c * 256, lane);
    }
    return warpSum(acc);
}

// ---------------------------------------------------------------------------
// K1: attn scores. warp-per-row (row = 1024 float4), 64 blocks x 8 warps.
__global__ void __launch_bounds__(256, 3)
k_attn_scores(const int* __restrict__ token, const float* __restrict__ hidden,
              const float* __restrict__ embedding,
              const float* __restrict__ attn_W, const float* __restrict__ attn_b) {
    __shared__ float4 sv[1024];
    int tid = threadIdx.x, lane = tid & 31, warp = tid >> 5;
    const float4* emb4 = (const float4*)(embedding + (size_t)__ldg(token) * H);
    const float4* hid4 = (const float4*)hidden;
#pragma unroll
    for (int k = 0; k < 2; k++) {
        int i = tid + 256 * k;
        sv[i] = __ldg(&emb4[i]);
        sv[i + 512] = __ldg(&hid4[i]);
    }
    __syncthreads();
    int row = blockIdx.x * 8 + warp;
    const float4* w4 = (const float4*)(attn_W + (size_t)row * 2 * H);
    float a = warpRowDot<4>(w4, sv, lane);
    if (lane == 0) g_scores[row] = a + __ldg(&attn_b[row]);
}

// ---------------------------------------------------------------------------
// K2: fused softmax + split-K context + last-block reduce (64 blocks).
__global__ void k_context(const float* __restrict__ enc,
                          float* __restrict__ out_aw) {
    __shared__ float s_e[L];
    __shared__ float sred[16];
    int tid = threadIdx.x, lane = tid & 31, warp = tid >> 5;
    float v0 = g_scores[tid], v1 = g_scores[tid + 256];
    float m = fmaxf(v0, v1);
#pragma unroll
    for (int o = 16; o; o >>= 1) m = fmaxf(m, __shfl_down_sync(0xffffffffu, m, o));
    if (lane == 0) sred[warp] = m;
    __syncthreads();
    if (warp == 0) {
        m = (lane < 8) ? sred[lane] : -1e30f;
#pragma unroll
        for (int o = 4; o; o >>= 1) m = fmaxf(m, __shfl_down_sync(0xffffffffu, m, o));
        if (lane == 0) sred[8] = m;
    }
    __syncthreads();
    m = sred[8];
    float e0 = expf(v0 - m), e1 = expf(v1 - m);
    s_e[tid] = e0;
    s_e[tid + 256] = e1;
    float sum = warpSum(e0 + e1);
    if (lane == 0) sred[warp] = sum;
    __syncthreads();
    if (warp == 0) {
        sum = (lane < 8) ? sred[lane] : 0.f;
        sum = warpSum(sum);
        if (lane == 0) sred[9] = sum;
    }
    __syncthreads();
    float inv = 1.f / sred[9];
    if (blockIdx.x == 0 && blockIdx.y == 0) {
        out_aw[tid] = s_e[tid] * inv;
        out_aw[tid + 256] = s_e[tid + 256] * inv;
    }
    int r0 = blockIdx.y * 64;
    int col = blockIdx.x * 256 + tid;
    float a0 = 0.f, a1 = 0.f, a2 = 0.f, a3 = 0.f;
#pragma unroll 4
    for (int l = 0; l < 64; l += 4) {
        a0 += s_e[r0 + l + 0] * __ldcs(&enc[(size_t)(r0 + l + 0) * H + col]);
        a1 += s_e[r0 + l + 1] * __ldcs(&enc[(size_t)(r0 + l + 1) * H + col]);
        a2 += s_e[r0 + l + 2] * __ldcs(&enc[(size_t)(r0 + l + 2) * H + col]);
        a3 += s_e[r0 + l + 3] * __ldcs(&enc[(size_t)(r0 + l + 3) * H + col]);
    }
    g_ctx_part[blockIdx.y * H + col] = ((a0 + a1) + (a2 + a3)) * inv;

    __threadfence();
    __shared__ bool isLast;
    if (tid == 0) isLast = (atomicAdd(&g_cnt_ctx, 1) == 63);
    __syncthreads();
    if (isLast) {
        const float4* p4 = (const float4*)g_ctx_part;
#pragma unroll
        for (int k = 0; k < 2; k++) {
            int i = tid + 256 * k;
            float4 c = p4[i];
#pragma unroll
            for (int p = 1; p < 8; p++) {
                float4 q = p4[p * (H / 4) + i];
                c.x += q.x; c.y += q.y; c.z += q.z; c.w += q.w;
            }
            ((float4*)g_ctx)[i] = c;
        }
        if (tid == 0) g_cnt_ctx = 0;
    }
}

// ---------------------------------------------------------------------------
// K3: combine. warp-per-row (row = 1024 float4), 256 blocks x 8 warps = 2048.
__global__ void __launch_bounds__(256, 3)
k_combine(const int* __restrict__ token, const float* __restrict__ embedding,
          const float* __restrict__ comb_W, const float* __restrict__ comb_b) {
    __shared__ float4 sv[1024];
    int tid = threadIdx.x, lane = tid & 31, warp = tid >> 5;
    const float4* emb4 = (const float4*)(embedding + (size_t)__ldg(token) * H);
    const float4* ctx4 = (const float4*)g_ctx;
#pragma unroll
    for (int k = 0; k < 2; k++) {
        int i = tid + 256 * k;
        sv[i] = __ldg(&emb4[i]);
        sv[i + 512] = __ldg(&ctx4[i]);
    }
    __syncthreads();
    int row = blockIdx.x * 8 + warp;
    const float4* w4 = (const float4*)(comb_W + (size_t)row * 2 * H);
    float a = warpRowDot<4>(w4, sv, lane);
    if (lane == 0) g_x[row] = fmaxf(a + __ldg(&comb_b[row]), 0.f);
}

// ---------------------------------------------------------------------------
// K4: GRU gates, persistent + cross-row-prefetch pipeline.
// 384 blocks x 8 warps = 3072 warps, exactly 4 rows each (stride 3072).
__global__ void __launch_bounds__(256, 3)
k_gates(const float* __restrict__ w_ih, const float* __restrict__ w_hh,
        const float* __restrict__ b_ih, const float* __restrict__ b_hh,
        const float* __restrict__ hidden) {
    __shared__ float4 sv[1024];   // [0:512)=x, [512:1024)=hidden
    int tid = threadIdx.x, lane = tid & 31, warp = tid >> 5;
    const float4* x4 = (const float4*)g_x;
    const float4* h4 = (const float4*)hidden;
#pragma unroll
    for (int k = 0; k < 2; k++) {
        int i = tid + 256 * k;
        sv[i] = __ldg(&x4[i]);
        sv[i + 512] = __ldg(&h4[i]);
    }
    __syncthreads();
    const int stride = NB_GATES * 8;  // 3072
    int row = blockIdx.x * 8 + warp;
    float4 A[8], B[8];
    const float4* wp = (row < 3 * H)
        ? (const float4*)(w_ih + (size_t)row * H)
        : (const float4*)(w_hh + (size_t)(row - 3 * H) * H);
    loadChunk(A, wp, lane);
#pragma unroll
    for (int it = 0; it < 4; it++) {
        int nrow = row + stride;
        int prow = (it < 3) ? nrow : row;        // clamp last prefetch
        const float4* wpn = (prow < 3 * H)
            ? (const float4*)(w_ih + (size_t)prow * H)
            : (const float4*)(w_hh + (size_t)(prow - 3 * H) * H);
        const float4* svb = (row < 3 * H) ? sv : sv + 512;
        loadChunk(B, wp + 256, lane);            // this row chunk1
        float acc = dotChunk(A, svb, lane);
        loadChunk(A, wpn, lane);                 // next row chunk0
        acc += dotChunk(B, svb + 256, lane);
        float a = warpSum(acc);
        if (lane == 0) {
            bool ih = row < 3 * H;
            int lrow = ih ? row : row - 3 * H;
            g_gates[row] = a + __ldg(ih ? &b_ih[lrow] : &b_hh[lrow]);
        }
        row = nrow;
        wp = wpn;
    }
}

// ---------------------------------------------------------------------------
// K5: GRU gate combine -> h_new
__global__ void k_hnew(const float* __restrict__ hidden, float* __restrict__ out_h) {
    int i = blockIdx.x * blockDim.x + threadIdx.x;
    if (i >= H) return;
    const float* gi = g_gates;
    const float* gh = g_gates + 3 * H;
    float r = 1.f / (1.f + expf(-(gi[i] + gh[i])));
    float z = 1.f / (1.f + expf(-(gi[H + i] + gh[H + i])));
    float n = tanhf(gi[2 * H + i] + r * gh[2 * H + i]);
    float hn = (1.f - z) * n + z * hidden[i];
    g_hnew[i] = hn;
    out_h[i] = hn;
}

// ---------------------------------------------------------------------------
// K6: logits GEMV (412 MB), persistent + cross-row-prefetch pipeline.
__global__ void __launch_bounds__(256, 3)
k_logits(const float* __restrict__ out_W, const float* __restrict__ out_b,
         float* __restrict__ out) {
    __shared__ float4 sv[512];
    __shared__ float smm[8], sss[8];
    int tid = threadIdx.x, lane = tid & 31, warp = tid >> 5;
    const float4* v4 = (const float4*)g_hnew;
#pragma unroll
    for (int k = 0; k < 2; k++) sv[tid + 256 * k] = __ldg(&v4[tid + 256 * k]);
    __syncthreads();
    const int stride = NB_LOGITS * 8;  // 3552
    int row = blockIdx.x * 8 + warp;
    float pm = -1e30f, ps = 0.f;
    if (row < V) {
        float4 A[8], B[8];
        const float4* wp = (const float4*)(out_W + (size_t)row * H);
        loadChunk(A, wp, lane);
        while (true) {
            int nrow = row + stride;
            int prow = (nrow < V) ? nrow : row;  // clamp last prefetch
            const float4* wpn = (const float4*)(out_W + (size_t)prow * H);
            loadChunk(B, wp + 256, lane);
            float acc = dotChunk(A, sv, lane);
            loadChunk(A, wpn, lane);
            acc += dotChunk(B, sv + 256, lane);
            float a = warpSum(acc);
            if (lane == 0) {
                float val = a + __ldg(&out_b[row]);
                out[row] = val;
                float M = fmaxf(pm, val);
                ps = ps * expf(pm - M) + expf(val - M);
                pm = M;
            }
            if (nrow >= V) break;
            row = nrow;
            wp = wpn;
        }
    }
    if (lane == 0) { smm[warp] = pm; sss[warp] = ps; }
    __syncthreads();
    if (tid == 0) {
        float m = smm[0], s = sss[0];
#pragma unroll
        for (int k = 1; k < 8; k++) {
            float M = fmaxf(m, smm[k]);
            s = s * expf(m - M) + sss[k] * expf(smm[k] - M);
            m = M;
        }
        g_lmax[blockIdx.x] = m;
        g_lsum[blockIdx.x] = s;
    }
}

// ---------------------------------------------------------------------------
// K7: merge 444 block partials -> g_lse (1 block, 256 threads)
__global__ void k_lse_merge() {
    __shared__ float smm[8], sss[8];
    int tid = threadIdx.x, lane = tid & 31, warp = tid >> 5;
    float m = -1e30f, s = 0.f;
    for (int i = tid; i < NB_LOGITS; i += 256) {
        float m2 = g_lmax[i], s2 = g_lsum[i];
        float M = fmaxf(m, m2);
        s = s * expf(m - M) + s2 * expf(m2 - M);
        m = M;
    }
#pragma unroll
    for (int o = 16; o; o >>= 1) {
        float m2 = __shfl_down_sync(0xffffffffu, m, o);
        float s2 = __shfl_down_sync(0xffffffffu, s, o);
        float M = fmaxf(m, m2);
        s = s * expf(m - M) + s2 * expf(m2 - M);
        m = M;
    }
    if (lane == 0) { smm[warp] = m; sss[warp] = s; }
    __syncthreads();
    if (tid == 0) {
        m = smm[0]; s = sss[0];
#pragma unroll
        for (int k = 1; k < 8; k++) {
            float M = fmaxf(m, smm[k]);
            s = s * expf(m - M) + sss[k] * expf(smm[k] - M);
            m = M;
        }
        g_lse[0] = m + logf(s);
    }
}

// K8: out[v] -= lse
__global__ void k_logsoftmax(float* __restrict__ out) {
    int i = blockIdx.x * blockDim.x + threadIdx.x;
    if (i < V) out[i] -= g_lse[0];
}

extern "C" void kernel_launch(void* const* d_in, const int* in_sizes, int n_in,
                              void* d_out, int out_size) {
    const int*   token     = (const int*)d_in[0];
    const float* hidden    = (const float*)d_in[1];
    const float* enc       = (const float*)d_in[2];
    const float* embedding = (const float*)d_in[3];
    const float* attn_W    = (const float*)d_in[4];
    const float* attn_b    = (const float*)d_in[5];
    const float* comb_W    = (const float*)d_in[6];
    const float* comb_b    = (const float*)d_in[7];
    const float* w_ih      = (const float*)d_in[8];
    const float* w_hh      = (const float*)d_in[9];
    const float* b_ih      = (const float*)d_in[10];
    const float* b_hh      = (const float*)d_in[11];
    const float* out_W     = (const float*)d_in[12];
    const float* out_b     = (const float*)d_in[13];

    float* out = (float*)d_out;
    float* out_logits = out;
    float* out_h      = out + V;
    float* out_aw     = out + V + H;

    k_attn_scores<<<L / 8, 256>>>(token, hidden, embedding, attn_W, attn_b);
    k_context<<<dim3(8, 8), 256>>>(enc, out_aw);
    k_combine<<<H / 8, 256>>>(token, embedding, comb_W, comb_b);
    k_gates<<<NB_GATES, 256>>>(w_ih, w_hh, b_ih, b_hh, hidden);
    k_hnew<<<H / 256, 256>>>(hidden, out_h);
    k_logits<<<NB_LOGITS, 256>>>(out_W, out_b, out_logits);
    k_lse_merge<<<1, 256>>>();
    k_logsoftmax<<<(V + 255) / 256, 256>>>(out_logits);
}